// round 16
// baseline (speedup 1.0000x reference)
#include <cuda_runtime.h>
#include <cstddef>

// PCEN transform:
//   m_t = (1-S)*m_{t-1} + S*x_t   (EMA over time axis, per [b,f] row)
//   out = (x / (m+EPS)^ALPHA + DELTA)^R - DELTA^R,  R = 0.5
//
// R15: R11 shape (warp per row, 8 elems/lane, CHUNK=256) +
//  - __ldcs / __stcs streaming (evict-first) hints on both touch-once streams
//  - pointer-increment addressing (no per-iter IMAD index math)
//  - peeled prefetch loop (no in-loop bounds predicate)
// Recurrence on q-scale (q_t = c*q_{t-1} + x_t, m = S*q); affine warp scan;
// exclusive prefix arithmetically: excl = (v - b) * c^-8.

#define S_CONST     0.025f
#define C_CONST     0.975f
#define EPS_CONST   1e-6f
#define ALPHA_CONST 0.98f
#define DELTA_CONST 2.0f
#define SQRT_DELTA  1.41421356237309515f   // sqrt(2)

#define T_LEN   4096
#define CHUNK   256               // elements per warp-chunk (32 lanes x 8)
#define NCHUNK  (T_LEN / CHUNK)   // 16
#define WARPS_PER_BLOCK 8
#define BLOCK_THREADS   (WARPS_PER_BLOCK * 32)

__device__ __forceinline__ float ex2_approx(float a) {
    float r; asm("ex2.approx.f32 %0, %1;" : "=f"(r) : "f"(a)); return r;
}
__device__ __forceinline__ float lg2_approx(float a) {
    float r; asm("lg2.approx.f32 %0, %1;" : "=f"(r) : "f"(a)); return r;
}
__device__ __forceinline__ float sqrt_approx(float a) {
    float r; asm("sqrt.approx.f32 %0, %1;" : "=f"(r) : "f"(a)); return r;
}

// fused epilogue on q-scale: m = S*q
//   (x * (S*q + EPS)^-ALPHA + DELTA)^0.5 - DELTA^0.5
__device__ __forceinline__ float pcen_epilogue(float xv, float q) {
    float p = ex2_approx(-ALPHA_CONST * lg2_approx(fmaf(S_CONST, q, EPS_CONST)));
    return sqrt_approx(fmaf(xv, p, DELTA_CONST)) - SQRT_DELTA;
}

// decay powers as compile-time constants
#define F1_C   0.816536509f                 /* 0.975^8  */
#define F2_C   (F1_C * F1_C)                /* c^16 */
#define F3_C   (F2_C * F2_C)                /* c^32 */
#define F4_C   (F3_C * F3_C)                /* c^64 */
#define F5_C   (F4_C * F4_C)                /* c^128 */
#define CCHK_C (F5_C * F5_C)                /* c^256 */
#define INV_F1 (1.0f / F1_C)                /* c^-8 */

struct Chunk { float4 a, b; };

__device__ __forceinline__ Chunk load_chunk_cs(const float* p) {
    Chunk c;
    c.a = __ldcs(reinterpret_cast<const float4*>(p));
    c.b = __ldcs(reinterpret_cast<const float4*>(p) + 1);
    return c;
}

// Process one 256-elem chunk: scan + epilogue + streaming store.
__device__ __forceinline__ void process_chunk(const Chunk& xc, float& carry,
                                              float clane, int lane, float* od)
{
    // local q-recurrence over this lane's 8 elements (zero-init)
    float b = xc.a.x;
    b = fmaf(C_CONST, b, xc.a.y);
    b = fmaf(C_CONST, b, xc.a.z);
    b = fmaf(C_CONST, b, xc.a.w);
    b = fmaf(C_CONST, b, xc.b.x);
    b = fmaf(C_CONST, b, xc.b.y);
    b = fmaf(C_CONST, b, xc.b.z);
    b = fmaf(C_CONST, b, xc.b.w);

    // inclusive affine warp scan: v_l = b_l + c^8 * v_{l-1}
    float v = b, u;
    u = __shfl_up_sync(0xffffffffu, v, 1);  if (lane >= 1)  v = fmaf(F1_C, u, v);
    u = __shfl_up_sync(0xffffffffu, v, 2);  if (lane >= 2)  v = fmaf(F2_C, u, v);
    u = __shfl_up_sync(0xffffffffu, v, 4);  if (lane >= 4)  v = fmaf(F3_C, u, v);
    u = __shfl_up_sync(0xffffffffu, v, 8);  if (lane >= 8)  v = fmaf(F4_C, u, v);
    u = __shfl_up_sync(0xffffffffu, v, 16); if (lane >= 16) v = fmaf(F5_C, u, v);

    // exclusive prefix arithmetically (exact 0 at lane 0)
    float excl = (v - b) * INV_F1;

    // fold cross-chunk carry
    float q = fmaf(clane, carry, excl);

    // carry for next chunk (lane 31 broadcast)
    float v31 = __shfl_sync(0xffffffffu, v, 31);
    carry = fmaf(CCHK_C, carry, v31);

    // reconstruct q per element + fused epilogue
    float4 oa, ob;
    q = fmaf(C_CONST, q, xc.a.x);  oa.x = pcen_epilogue(xc.a.x, q);
    q = fmaf(C_CONST, q, xc.a.y);  oa.y = pcen_epilogue(xc.a.y, q);
    q = fmaf(C_CONST, q, xc.a.z);  oa.z = pcen_epilogue(xc.a.z, q);
    q = fmaf(C_CONST, q, xc.a.w);  oa.w = pcen_epilogue(xc.a.w, q);
    q = fmaf(C_CONST, q, xc.b.x);  ob.x = pcen_epilogue(xc.b.x, q);
    q = fmaf(C_CONST, q, xc.b.y);  ob.y = pcen_epilogue(xc.b.y, q);
    q = fmaf(C_CONST, q, xc.b.z);  ob.z = pcen_epilogue(xc.b.z, q);
    q = fmaf(C_CONST, q, xc.b.w);  ob.w = pcen_epilogue(xc.b.w, q);

    __stcs(reinterpret_cast<float4*>(od),     oa);
    __stcs(reinterpret_cast<float4*>(od) + 1, ob);
}

__global__ __launch_bounds__(BLOCK_THREADS, 7)
void pcen_kernel(const float* __restrict__ x, float* __restrict__ out, int nrows)
{
    const int gwarp = (blockIdx.x * BLOCK_THREADS + threadIdx.x) >> 5;
    const int lane  = threadIdx.x & 31;
    if (gwarp >= nrows) return;

    const float* xp = x   + (size_t)gwarp * T_LEN + lane * 8;
    float*       op = out + (size_t)gwarp * T_LEN + lane * 8;

    // c^(8*lane) via MUFU (once per thread)
    const float clane = ex2_approx(8.0f * (float)lane * lg2_approx(C_CONST));

    float carry = 0.0f;

    // software pipeline: chunk 0 in flight before the loop
    Chunk cur = load_chunk_cs(xp);
    xp += CHUNK;

    #pragma unroll 1
    for (int ch = 0; ch < NCHUNK - 1; ++ch) {
        Chunk nxt = load_chunk_cs(xp);      // prefetch next chunk
        xp += CHUNK;
        process_chunk(cur, carry, clane, lane, op);
        op += CHUNK;
        cur = nxt;
    }
    // final chunk (no prefetch)
    process_chunk(cur, carry, clane, lane, op);
}

extern "C" void kernel_launch(void* const* d_in, const int* in_sizes, int n_in,
                              void* d_out, int out_size)
{
    const float* x = (const float*)d_in[0];
    float* out = (float*)d_out;

    int nrows  = in_sizes[0] / T_LEN;                              // 8192
    int blocks = (nrows + WARPS_PER_BLOCK - 1) / WARPS_PER_BLOCK;  // 1024

    pcen_kernel<<<blocks, BLOCK_THREADS>>>(x, out, nrows);
}